// round 4
// baseline (speedup 1.0000x reference)
#include <cuda_runtime.h>
#include <cstdint>

// Problem constants
#define BB    128
#define LL    9
#define KK    3
#define CIN   256
#define COUT  256
#define PP    1680
#define NSUB  84          // C(9,3)
#define PSPLIT 4
#define PCHUNK (PP / PSPLIT)   // 420

// Scratch (static device arrays only — no allocations allowed)
__device__ float g_Z[BB * LL * KK * COUT];   // [b][l][a][o]  3.54 MB
__device__ int   g_sids[PP];                 // packed subset ranks per permutation

// Packed fp32x2 FMA (Blackwell FFMA2) — 2x fp32 rate vs scalar FFMA
__device__ __forceinline__ void ffma2(unsigned long long& d,
                                      unsigned long long a,
                                      unsigned long long b) {
    asm("fma.rn.f32x2 %0, %1, %2, %0;" : "+l"(d) : "l"(a), "l"(b));
}

// ---------------------------------------------------------------------------
// Kernel A: derive per-permutation subset ranks from the binary mask M.
// For each p: mask_a = bits l where M[a,p,l]==1  (a 3-subset of 9).
// Rank in increasing-mask (colex) order: rank = l1 + C(l2,2) + C(l3,3).
// Pack 3 ranks (<=83) into one int, 10 bits each.
// ---------------------------------------------------------------------------
__global__ void sid_kernel(const float* __restrict__ M) {
    int p = blockIdx.x * blockDim.x + threadIdx.x;
    if (p >= PP) return;
    int packed = 0;
#pragma unroll
    for (int a = 0; a < KK; a++) {
        int mask = 0;
#pragma unroll
        for (int l = 0; l < LL; l++)
            if (M[(a * PP + p) * LL + l] > 0.5f) mask |= (1 << l);
        int m  = mask;
        int l1 = __ffs(m) - 1; m &= m - 1;
        int l2 = __ffs(m) - 1; m &= m - 1;
        int l3 = __ffs(m) - 1;
        int rank = l1 + (l2 * (l2 - 1)) / 2 + (l3 * (l3 - 1) * (l3 - 2)) / 6;
        packed |= rank << (a * 10);
    }
    g_sids[p] = packed;
}

// ---------------------------------------------------------------------------
// Kernel B: Z[b,l,a,o] = sum_c x[b,l,c] * W[a,o,c]
// One block per b. x[b] (9x256, 9 KB) in shared, broadcast via LDS.128.
// Each thread owns one o and all 3 a's (27 accumulators as f32x2 pairs).
// ---------------------------------------------------------------------------
__global__ void __launch_bounds__(256, 1)
z_kernel(const float* __restrict__ x, const float* __restrict__ W) {
    __shared__ ulonglong2 xs[LL * 64];   // [l][c4] : 9 KB
    int b   = blockIdx.x;
    int tid = threadIdx.x;

    const ulonglong2* xg = reinterpret_cast<const ulonglong2*>(x + (size_t)b * LL * CIN);
    for (int i = tid; i < LL * 64; i += 256) xs[i] = xg[i];
    __syncthreads();

    // column o = tid ; rows W[a][o][:] for a = 0..2
    const ulonglong2* w0 = reinterpret_cast<const ulonglong2*>(W) + (size_t)tid * 64;

    unsigned long long acc[KK][LL];
#pragma unroll
    for (int j = 0; j < KK; j++)
#pragma unroll
        for (int l = 0; l < LL; l++) acc[j][l] = 0ull;

#pragma unroll 2
    for (int c4 = 0; c4 < 64; c4++) {
        ulonglong2 w[KK];
        w[0] = w0[c4];
        w[1] = w0[64 * COUT + c4];
        w[2] = w0[2 * 64 * COUT + c4];
#pragma unroll
        for (int l = 0; l < LL; l++) {
            ulonglong2 xv = xs[l * 64 + c4];
#pragma unroll
            for (int j = 0; j < KK; j++) {
                ffma2(acc[j][l], w[j].x, xv.x);
                ffma2(acc[j][l], w[j].y, xv.y);
            }
        }
    }

#pragma unroll
    for (int j = 0; j < KK; j++)
#pragma unroll
        for (int l = 0; l < LL; l++) {
            float2 f = *reinterpret_cast<float2*>(&acc[j][l]);
            g_Z[((b * LL + l) * KK + j) * COUT + tid] = f.x + f.y;
        }
}

// ---------------------------------------------------------------------------
// Kernel C: y[b,p,o] = T0[s0(p)][o] + T1[s1(p)][o] + T2[s2(p)][o]
// where T_a[s][o] = sum_{l in subset s} Z[b,l,a,o].
// Block = (b, channel-half, p-chunk). T tables (3*84*128ch fp32 = 129 KB)
// live in dynamic shared. 3 LDS.128 + 1 streaming STG.128 per output float4.
// ---------------------------------------------------------------------------
#define SMEM_TT  (3 * NSUB * 32 * 16)        // 129024
#define SMEM_ZS  (27 * 32 * 16)              // 13824
#define SMEM_M84 (96 * 4)                    // 384 (84 used, padded)
#define SMEM_PS  (PCHUNK * 4)                // 1680
#define SMEM_C   (SMEM_TT + SMEM_ZS + SMEM_M84 + SMEM_PS)   // 144912

__global__ void __launch_bounds__(512, 1)
y_kernel(float4* __restrict__ out) {
    extern __shared__ char smem[];
    float4* Tt   = reinterpret_cast<float4*>(smem);
    float4* Zs   = reinterpret_cast<float4*>(smem + SMEM_TT);
    int*    m84  = reinterpret_cast<int*>(smem + SMEM_TT + SMEM_ZS);
    int*    psid = m84 + 96;

    int tid = threadIdx.x;
    int b   = blockIdx.x;
    int oh  = blockIdx.y;     // channel half: 0 or 1 (128 channels each)
    int p0  = blockIdx.z * PCHUNK;

    // Load Z slice for (b, oh): 27 rows x 32 float4
    const float4* gZ4 = reinterpret_cast<const float4*>(g_Z);
    for (int i = tid; i < 27 * 32; i += 512)
        Zs[i] = gZ4[(b * 27 + (i >> 5)) * 64 + oh * 32 + (i & 31)];

    // Load this chunk's packed subset ranks
    for (int i = tid; i < PCHUNK; i += 512) psid[i] = g_sids[p0 + i];

    // Enumerate the 84 3-subset masks in increasing order (matches colex rank)
    if (tid == 0) {
        int c = 0;
        for (int m = 7; m < 512; m++)
            if (__popc(m) == 3) m84[c++] = m;
    }
    __syncthreads();

    // Build T: 252 rows x 32 float4
    for (int i = tid; i < 3 * NSUB * 32; i += 512) {
        int row = i >> 5, o4 = i & 31;
        int a   = row / NSUB;
        int sid = row - a * NSUB;
        int m   = m84[sid];
        int l1 = __ffs(m) - 1; m &= m - 1;
        int l2 = __ffs(m) - 1; m &= m - 1;
        int l3 = __ffs(m) - 1;
        float4 v1 = Zs[(l1 * 3 + a) * 32 + o4];
        float4 v2 = Zs[(l2 * 3 + a) * 32 + o4];
        float4 v3 = Zs[(l3 * 3 + a) * 32 + o4];
        float4 s;
        s.x = v1.x + v2.x + v3.x;
        s.y = v1.y + v2.y + v3.y;
        s.z = v1.z + v2.z + v3.z;
        s.w = v1.w + v2.w + v3.w;
        Tt[i] = s;
    }
    __syncthreads();

    // Gather phase: each warp iterates permutations, lanes cover 32 float4 (128 ch)
    int lane = tid & 31, pr = tid >> 5;   // 16 warps
    for (int i = pr; i < PCHUNK; i += 16) {
        int sp = psid[i];
        int s0 =  sp        & 1023;
        int s1 = (sp >> 10) & 1023;
        int s2 =  sp >> 20;
        float4 a0 = Tt[(s0) * 32 + lane];
        float4 a1 = Tt[(NSUB + s1) * 32 + lane];
        float4 a2 = Tt[(2 * NSUB + s2) * 32 + lane];
        float4 r;
        r.x = a0.x + a1.x + a2.x;
        r.y = a0.y + a1.y + a2.y;
        r.z = a0.z + a1.z + a2.z;
        r.w = a0.w + a1.w + a2.w;
        // streaming store — output is write-once, keep it out of L2 as much as possible
        __stcs(&out[(size_t)(b * PP + p0 + i) * 64 + oh * 32 + lane], r);
    }
}

// ---------------------------------------------------------------------------
extern "C" void kernel_launch(void* const* d_in, const int* in_sizes, int n_in,
                              void* d_out, int out_size) {
    (void)in_sizes; (void)n_in; (void)out_size;
    const float* x = (const float*)d_in[0];
    const float* W = (const float*)d_in[1];
    const float* M = (const float*)d_in[2];
    float4* y = (float4*)d_out;

    cudaFuncSetAttribute(y_kernel, cudaFuncAttributeMaxDynamicSharedMemorySize, SMEM_C);

    sid_kernel<<<(PP + 255) / 256, 256>>>(M);
    z_kernel<<<BB, 256>>>(x, W);
    dim3 grid(BB, 2, PSPLIT);
    y_kernel<<<grid, 512, SMEM_C>>>(y);
}

// round 5
// speedup vs baseline: 1.5842x; 1.5842x over previous
#include <cuda_runtime.h>
#include <cstdint>

// Problem constants
#define BB    128
#define LL    9
#define KK    3
#define CIN   256
#define COUT  256
#define PP    1680
#define NSUB  84          // C(9,3)

// Scratch (static device arrays only — no allocations allowed)
__device__ float g_Z[BB * LL * KK * COUT];   // [b][l][a][o]  3.54 MB
__device__ int   g_sids[PP];                 // packed subset ranks per permutation

// Packed fp32x2 FMA (Blackwell FFMA2) — 2x fp32 rate vs scalar FFMA
__device__ __forceinline__ void ffma2(unsigned long long& d,
                                      unsigned long long a,
                                      unsigned long long b) {
    asm("fma.rn.f32x2 %0, %1, %2, %0;" : "+l"(d) : "l"(a), "l"(b));
}

// ---------------------------------------------------------------------------
// Kernel A: derive per-permutation subset ranks from the binary mask M.
// Coalesced: stage a 256-permutation tile of M into shared, then decode.
// Rank in increasing-mask (colex) order: rank = l1 + C(l2,2) + C(l3,3).
// Pack 3 ranks (<=83) into one int, 10 bits each.
// ---------------------------------------------------------------------------
__global__ void sid_kernel(const float* __restrict__ M) {
    __shared__ float Ms[KK][256 * LL];
    int p0  = blockIdx.x * 256;
    int np  = min(256, PP - p0);
    int tid = threadIdx.x;

#pragma unroll
    for (int a = 0; a < KK; a++) {
        const float* src = M + ((size_t)a * PP + p0) * LL;
        for (int i = tid; i < np * LL; i += 256) Ms[a][i] = src[i];
    }
    __syncthreads();

    if (tid < np) {
        int packed = 0;
#pragma unroll
        for (int a = 0; a < KK; a++) {
            int mask = 0;
#pragma unroll
            for (int l = 0; l < LL; l++)
                if (Ms[a][tid * LL + l] > 0.5f) mask |= (1 << l);
            int m  = mask;
            int l1 = __ffs(m) - 1; m &= m - 1;
            int l2 = __ffs(m) - 1; m &= m - 1;
            int l3 = __ffs(m) - 1;
            int rank = l1 + (l2 * (l2 - 1)) / 2 + (l3 * (l3 - 1) * (l3 - 2)) / 6;
            packed |= rank << (a * 10);
        }
        g_sids[p0 + tid] = packed;
    }
}

// ---------------------------------------------------------------------------
// Kernel B: Z[b,l,a,o] = sum_c x[b,l,c] * W[a,o,c]
// One block per b. x[b] (9x256, 9 KB) in shared, broadcast via LDS.128.
// Each thread owns one o and all 3 a's (27 accumulators as f32x2 pairs).
// ---------------------------------------------------------------------------
__global__ void __launch_bounds__(256, 1)
z_kernel(const float* __restrict__ x, const float* __restrict__ W) {
    __shared__ ulonglong2 xs[LL * 64];   // [l][c4] : 9 KB
    int b   = blockIdx.x;
    int tid = threadIdx.x;

    const ulonglong2* xg = reinterpret_cast<const ulonglong2*>(x + (size_t)b * LL * CIN);
    for (int i = tid; i < LL * 64; i += 256) xs[i] = xg[i];
    __syncthreads();

    const ulonglong2* w0 = reinterpret_cast<const ulonglong2*>(W) + (size_t)tid * 64;

    unsigned long long acc[KK][LL];
#pragma unroll
    for (int j = 0; j < KK; j++)
#pragma unroll
        for (int l = 0; l < LL; l++) acc[j][l] = 0ull;

#pragma unroll 2
    for (int c4 = 0; c4 < 64; c4++) {
        ulonglong2 w[KK];
        w[0] = w0[c4];
        w[1] = w0[64 * COUT + c4];
        w[2] = w0[2 * 64 * COUT + c4];
#pragma unroll
        for (int l = 0; l < LL; l++) {
            ulonglong2 xv = xs[l * 64 + c4];
#pragma unroll
            for (int j = 0; j < KK; j++) {
                ffma2(acc[j][l], w[j].x, xv.x);
                ffma2(acc[j][l], w[j].y, xv.y);
            }
        }
    }

#pragma unroll
    for (int j = 0; j < KK; j++)
#pragma unroll
        for (int l = 0; l < LL; l++) {
            float2 f = *reinterpret_cast<float2*>(&acc[j][l]);
            g_Z[((b * LL + l) * KK + j) * COUT + tid] = f.x + f.y;
        }
}

// ---------------------------------------------------------------------------
// Kernel C: y[b,p,o] = T0[s0(p)][o] + T1[s1(p)][o] + T2[s2(p)][o]
// where T_a[s][o] = sum_{l in subset s} Z[b,l,a,o].
//
// v2: channel QUARTERS (64 ch) instead of halves -> smem 78.5 KB/block ->
// 2 blocks/SM; PSPLIT removed (each block covers all 1680 p, T built once).
// Grid = (128 b, 4 quarters) = 512 blocks (~1.7 waves at occ 2).
// Warp covers 2 permutations per iteration (16 lanes x float4 each).
// ---------------------------------------------------------------------------
#define OCH      16                              // float4 per quarter (64 floats)
#define SMEM_TT  (3 * NSUB * OCH * 16)           // 64512
#define SMEM_ZS  (27 * OCH * 16)                 // 6912
#define SMEM_M84 (96 * 4)                        // 384 (84 used, padded)
#define SMEM_PS  (PP * 4)                        // 6720
#define SMEM_C   (SMEM_TT + SMEM_ZS + SMEM_M84 + SMEM_PS)   // 78528

__global__ void __launch_bounds__(512, 2)
y_kernel(float4* __restrict__ out) {
    extern __shared__ char smem[];
    float4* Tt   = reinterpret_cast<float4*>(smem);
    float4* Zs   = reinterpret_cast<float4*>(smem + SMEM_TT);
    int*    m84  = reinterpret_cast<int*>(smem + SMEM_TT + SMEM_ZS);
    int*    psid = m84 + 96;

    int tid = threadIdx.x;
    int b   = blockIdx.x;
    int oq  = blockIdx.y;     // channel quarter: 0..3 (64 channels each)

    // Load Z slice for (b, oq): 27 rows x 16 float4
    const float4* gZ4 = reinterpret_cast<const float4*>(g_Z);
    for (int i = tid; i < 27 * OCH; i += 512)
        Zs[i] = gZ4[(b * 27 + (i >> 4)) * 64 + oq * OCH + (i & 15)];

    // Load all packed subset ranks
    for (int i = tid; i < PP; i += 512) psid[i] = g_sids[i];

    // Enumerate the 84 3-subset masks in increasing order (matches colex rank)
    if (tid == 0) {
        int c = 0;
        for (int m = 7; m < 512; m++)
            if (__popc(m) == 3) m84[c++] = m;
    }
    __syncthreads();

    // Build T: 252 rows x 16 float4
    for (int i = tid; i < 3 * NSUB * OCH; i += 512) {
        int row = i >> 4, o4 = i & 15;
        int a   = row / NSUB;
        int sid = row - a * NSUB;
        int m   = m84[sid];
        int l1 = __ffs(m) - 1; m &= m - 1;
        int l2 = __ffs(m) - 1; m &= m - 1;
        int l3 = __ffs(m) - 1;
        float4 v1 = Zs[(l1 * 3 + a) * OCH + o4];
        float4 v2 = Zs[(l2 * 3 + a) * OCH + o4];
        float4 v3 = Zs[(l3 * 3 + a) * OCH + o4];
        float4 s;
        s.x = v1.x + v2.x + v3.x;
        s.y = v1.y + v2.y + v3.y;
        s.z = v1.z + v2.z + v3.z;
        s.w = v1.w + v2.w + v3.w;
        Tt[i] = s;
    }
    __syncthreads();

    // Gather phase: 16 warps, each iteration a warp handles 2 permutations
    // (lanes 0-15 -> p, lanes 16-31 -> p+1), 16 float4 = 64 channels each.
    int lane = tid & 31, wid = tid >> 5;
    int half = lane >> 4, l15 = lane & 15;
    for (int i = wid; i < PP / 2; i += 16) {
        int p  = 2 * i + half;
        int sp = psid[p];
        int s0 =  sp        & 1023;
        int s1 = (sp >> 10) & 1023;
        int s2 =  sp >> 20;
        float4 a0 = Tt[(s0) * OCH + l15];
        float4 a1 = Tt[(NSUB + s1) * OCH + l15];
        float4 a2 = Tt[(2 * NSUB + s2) * OCH + l15];
        float4 r;
        r.x = a0.x + a1.x + a2.x;
        r.y = a0.y + a1.y + a2.y;
        r.z = a0.z + a1.z + a2.z;
        r.w = a0.w + a1.w + a2.w;
        // streaming store — output is write-once, keep it out of L2
        __stcs(&out[(size_t)(b * PP + p) * 64 + oq * OCH + l15], r);
    }
}

// ---------------------------------------------------------------------------
extern "C" void kernel_launch(void* const* d_in, const int* in_sizes, int n_in,
                              void* d_out, int out_size) {
    (void)in_sizes; (void)n_in; (void)out_size;
    const float* x = (const float*)d_in[0];
    const float* W = (const float*)d_in[1];
    const float* M = (const float*)d_in[2];
    float4* y = (float4*)d_out;

    cudaFuncSetAttribute(y_kernel, cudaFuncAttributeMaxDynamicSharedMemorySize, SMEM_C);

    sid_kernel<<<(PP + 255) / 256, 256>>>(M);
    z_kernel<<<BB, 256>>>(x, W);
    dim3 grid(BB, 4);
    y_kernel<<<grid, 512, SMEM_C>>>(y);
}